// round 2
// baseline (speedup 1.0000x reference)
#include <cuda_runtime.h>

#define TT 64
#define CC 128
#define HD 32
#define XS 132      // x smem stride (mult of 4 -> LDS.128 aligned)
#define WS 96       // W smem row stride (rows = 128 dims, cols q|k|v)
#define QVS 68      // q/v smem stride (q cols 0-31, v cols 32-63)
#define KTS 68      // kT stride: kT[dim][seqrow]
#define SCS 65      // scores stride (overlays xs)
#define NTHREADS 256

// smem float offsets
#define OFF_XS   0
#define OFF_W    (TT * XS)                 // 8448
#define OFF_QV   (OFF_W + CC * WS)         // 20736
#define OFF_KT   (OFF_QV + TT * QVS)       // 25088
#define SMEM_FLOATS (OFF_KT + HD * KTS)    // 27264 -> 109056 B

typedef unsigned long long u64;

__device__ __forceinline__ u64 splat2(float x) {
    u64 r;
    asm("mov.b64 %0, {%1, %1};" : "=l"(r) : "f"(x));
    return r;
}
__device__ __forceinline__ void ffma2(u64& d, u64 a, u64 b) {
    asm("fma.rn.f32x2 %0, %1, %2, %0;" : "+l"(d) : "l"(a), "l"(b));
}
__device__ __forceinline__ float2 unpack2(u64 a) {
    float lo, hi;
    asm("mov.b64 {%0, %1}, %2;" : "=f"(lo), "=f"(hi) : "l"(a));
    return make_float2(lo, hi);
}

__global__ __launch_bounds__(NTHREADS, 2)
void head_attn_kernel(const float* __restrict__ x,
                      const float* __restrict__ Wq,
                      const float* __restrict__ Wk,
                      const float* __restrict__ Wv,
                      float* __restrict__ out) {
    extern __shared__ float smem[];
    float* xs  = smem + OFF_XS;   // [64][132]; later scores [64][65]
    float* Wsm = smem + OFF_W;    // [128][96]
    float* qv  = smem + OFF_QV;   // [64][68]: q cols 0-31, v cols 32-63
    float* kT  = smem + OFF_KT;   // [32][68]: kT[dim][seqrow]

    const int tid = threadIdx.x;
    const int b   = blockIdx.x;
    const float* xb = x + (size_t)b * (TT * CC);

    // ---------------- Phase 0: stage x and W into smem ----------------
    for (int i = tid; i < (TT * CC) / 4; i += NTHREADS) {
        float4 v4 = reinterpret_cast<const float4*>(xb)[i];
        int idx = i * 4;
        int r = idx >> 7;
        int c = idx & 127;
        *reinterpret_cast<float4*>(xs + r * XS + c) = v4;
    }
    #pragma unroll
    for (int ii = 0; ii < (CC * HD) / 4 / NTHREADS; ii++) {   // 4 iters
        int i = tid + ii * NTHREADS;
        int idx = i * 4;
        int d = idx >> 5;
        int c = idx & 31;
        float4 vq = reinterpret_cast<const float4*>(Wq)[i];
        float4 vk = reinterpret_cast<const float4*>(Wk)[i];
        float4 vv = reinterpret_cast<const float4*>(Wv)[i];
        *reinterpret_cast<float4*>(Wsm + d * WS + c)      = vq;
        *reinterpret_cast<float4*>(Wsm + d * WS + 32 + c) = vk;
        *reinterpret_cast<float4*>(Wsm + d * WS + 64 + c) = vv;
    }
    __syncthreads();

    // ---------------- Phase 1: fused QKV projection (FFMA2) ----------------
    // [64,128]@[128,96]. Thread tile: 2 rows x 12 cols (6 packed accs/row).
    {
        const int ct = tid & 7;      // 8 col tiles * 12 = 96
        const int rt = tid >> 3;     // 32 row tiles * 2 = 64
        const int c0 = ct * 12;
        const int r0 = rt * 2;

        u64 acc[2][6];
        #pragma unroll
        for (int i = 0; i < 2; i++)
            #pragma unroll
            for (int p = 0; p < 6; p++) acc[i][p] = 0ull;

        const float* x0 = xs + r0 * XS;
        const float* x1 = xs + (r0 + 1) * XS;

        for (int d4 = 0; d4 < CC; d4 += 4) {
            float4 a0 = *reinterpret_cast<const float4*>(x0 + d4);
            float4 a1 = *reinterpret_cast<const float4*>(x1 + d4);
            float f0[4] = {a0.x, a0.y, a0.z, a0.w};
            float f1[4] = {a1.x, a1.y, a1.z, a1.w};
            const float* wr = Wsm + d4 * WS + c0;
            #pragma unroll
            for (int dd = 0; dd < 4; dd++) {
                const float* w = wr + dd * WS;
                ulonglong2 w0 = *reinterpret_cast<const ulonglong2*>(w);
                ulonglong2 w1 = *reinterpret_cast<const ulonglong2*>(w + 4);
                ulonglong2 w2 = *reinterpret_cast<const ulonglong2*>(w + 8);
                u64 s0 = splat2(f0[dd]);
                u64 s1 = splat2(f1[dd]);
                ffma2(acc[0][0], s0, w0.x); ffma2(acc[0][1], s0, w0.y);
                ffma2(acc[0][2], s0, w1.x); ffma2(acc[0][3], s0, w1.y);
                ffma2(acc[0][4], s0, w2.x); ffma2(acc[0][5], s0, w2.y);
                ffma2(acc[1][0], s1, w0.x); ffma2(acc[1][1], s1, w0.y);
                ffma2(acc[1][2], s1, w1.x); ffma2(acc[1][3], s1, w1.y);
                ffma2(acc[1][4], s1, w2.x); ffma2(acc[1][5], s1, w2.y);
            }
        }

        // scatter: q -> qv[:,0:32], k -> kT[dim][row], v -> qv[:,32:64]
        #pragma unroll
        for (int i = 0; i < 2; i++) {
            int r = r0 + i;
            #pragma unroll
            for (int p = 0; p < 6; p++) {
                float2 v2 = unpack2(acc[i][p]);
                int c = c0 + 2 * p;
                #pragma unroll
                for (int e = 0; e < 2; e++) {
                    float val = (e == 0) ? v2.x : v2.y;
                    int cc = c + e;
                    if (cc < 32)       qv[r * QVS + cc] = val;
                    else if (cc < 64)  kT[(cc - 32) * KTS + r] = val;
                    else               qv[r * QVS + (cc - 32)] = val;
                }
            }
        }
    }
    __syncthreads();

    // ---------------- Phase 2: scores = scale * q @ k^T (FFMA2) ----------------
    // 4 rows x 4 cols per thread; causal tile skip. scores overlay xs.
    {
        const int ct = tid & 15;
        const int rt = tid >> 4;
        const int c0 = ct * 4;
        const int r0 = rt * 4;
        float* sc = xs;

        if (c0 <= r0 + 3) {
            u64 acc[4][2];
            #pragma unroll
            for (int i = 0; i < 4; i++) { acc[i][0] = 0ull; acc[i][1] = 0ull; }

            for (int d4 = 0; d4 < HD; d4 += 4) {
                float qf[4][4];
                #pragma unroll
                for (int i = 0; i < 4; i++) {
                    float4 qq = *reinterpret_cast<const float4*>(qv + (r0 + i) * QVS + d4);
                    qf[i][0] = qq.x; qf[i][1] = qq.y; qf[i][2] = qq.z; qf[i][3] = qq.w;
                }
                #pragma unroll
                for (int dd = 0; dd < 4; dd++) {
                    ulonglong2 kk = *reinterpret_cast<const ulonglong2*>(kT + (d4 + dd) * KTS + c0);
                    #pragma unroll
                    for (int i = 0; i < 4; i++) {
                        u64 s = splat2(qf[i][dd]);
                        ffma2(acc[i][0], s, kk.x);
                        ffma2(acc[i][1], s, kk.y);
                    }
                }
            }

            const float scale = 0.17677669529663687f;  // 1/sqrt(32)
            #pragma unroll
            for (int i = 0; i < 4; i++) {
                #pragma unroll
                for (int p = 0; p < 2; p++) {
                    float2 v2 = unpack2(acc[i][p]);
                    sc[(r0 + i) * SCS + c0 + 2 * p]     = v2.x * scale;
                    sc[(r0 + i) * SCS + c0 + 2 * p + 1] = v2.y * scale;
                }
            }
        }
    }
    __syncthreads();

    // ---------------- Phase 3: causal softmax, one warp per row ----------------
    {
        const int w    = tid >> 5;
        const int lane = tid & 31;
        for (int r = w; r < TT; r += 8) {
            float* row = xs + r * SCS;
            bool v0 = (lane <= r);
            bool v1 = (lane + 32 <= r);
            float s0 = v0 ? row[lane]      : -1e30f;
            float s1 = v1 ? row[lane + 32] : -1e30f;
            float m = fmaxf(s0, s1);
            #pragma unroll
            for (int off = 16; off > 0; off >>= 1)
                m = fmaxf(m, __shfl_xor_sync(0xffffffffu, m, off));
            float e0 = v0 ? __expf(s0 - m) : 0.0f;
            float e1 = v1 ? __expf(s1 - m) : 0.0f;
            float sum = e0 + e1;
            #pragma unroll
            for (int off = 16; off > 0; off >>= 1)
                sum += __shfl_xor_sync(0xffffffffu, sum, off);
            float inv = 1.0f / sum;
            row[lane]      = e0 * inv;
            row[lane + 32] = e1 * inv;
        }
    }
    __syncthreads();

    // ---------------- Phase 4: out = probs @ v (FFMA2) ----------------
    // 2 rows x 4 head-cols per thread; causal loop truncation.
    {
        const int ct = tid & 7;
        const int rt = tid >> 3;
        const int h0 = ct * 4;
        const int r0 = rt * 2;

        u64 acc0[2] = {0ull, 0ull};
        u64 acc1[2] = {0ull, 0ull};
        const int cmax = r0 + 1;   // probs are exact zeros beyond row index

        for (int c = 0; c <= cmax; c++) {
            float p0 = xs[r0 * SCS + c];
            float p1 = xs[(r0 + 1) * SCS + c];
            ulonglong2 vv = *reinterpret_cast<const ulonglong2*>(qv + c * QVS + 32 + h0);
            u64 s0 = splat2(p0);
            u64 s1 = splat2(p1);
            ffma2(acc0[0], s0, vv.x); ffma2(acc0[1], s0, vv.y);
            ffma2(acc1[0], s1, vv.x); ffma2(acc1[1], s1, vv.y);
        }

        float* ob = out + (size_t)b * (TT * HD);
        float2 a00 = unpack2(acc0[0]), a01 = unpack2(acc0[1]);
        float2 a10 = unpack2(acc1[0]), a11 = unpack2(acc1[1]);
        *reinterpret_cast<float4*>(ob + r0 * HD + h0) =
            make_float4(a00.x, a00.y, a01.x, a01.y);
        *reinterpret_cast<float4*>(ob + (r0 + 1) * HD + h0) =
            make_float4(a10.x, a10.y, a11.x, a11.y);
    }
}

extern "C" void kernel_launch(void* const* d_in, const int* in_sizes, int n_in,
                              void* d_out, int out_size) {
    const float* x  = (const float*)d_in[0];
    const float* Wq = (const float*)d_in[1];
    const float* Wk = (const float*)d_in[2];
    const float* Wv = (const float*)d_in[3];
    float* out = (float*)d_out;

    const int B = in_sizes[0] / (TT * CC);   // 4096
    const size_t smem_bytes = SMEM_FLOATS * sizeof(float);

    static_assert(SMEM_FLOATS * sizeof(float) <= 113 * 1024, "smem budget for 2 CTAs/SM");
    cudaFuncSetAttribute(head_attn_kernel,
                         cudaFuncAttributeMaxDynamicSharedMemorySize,
                         (int)smem_bytes);

    head_attn_kernel<<<B, NTHREADS, smem_bytes>>>(x, Wq, Wk, Wv, out);
}